// round 13
// baseline (speedup 1.0000x reference)
#include <cuda_runtime.h>
#include <cuda_fp16.h>
#include <cstdint>

#define HF 64
#define MAX_NODES 100000

// Scratch tables in fp16: A[n] = h[n]@W1[:64] + b1,  B[n] = h[n]@W1[64:]
__device__ __half g_A[MAX_NODES * HF];
__device__ __half g_B[MAX_NODES * HF];
// Pre-transposed fp16 W': g_Wt[j*64+k] = W'(k,j); j<64 -> W1s, j>=64 -> W1d
__device__ __half g_Wt[128 * 64];

// ---------------- PTX helpers ----------------
__device__ __forceinline__ uint32_t smem_u32(const void* p) {
    uint32_t a;
    asm("{ .reg .u64 t; cvta.to.shared.u64 t, %1; cvt.u32.u64 %0, t; }"
        : "=r"(a) : "l"(p));
    return a;
}
__device__ __forceinline__ void ldsm_x4(uint32_t& r0, uint32_t& r1,
                                        uint32_t& r2, uint32_t& r3, uint32_t addr) {
    asm volatile("ldmatrix.sync.aligned.m8n8.x4.shared.b16 {%0,%1,%2,%3}, [%4];"
                 : "=r"(r0), "=r"(r1), "=r"(r2), "=r"(r3) : "r"(addr));
}
__device__ __forceinline__ void ldsm_x2(uint32_t& r0, uint32_t& r1, uint32_t addr) {
    asm volatile("ldmatrix.sync.aligned.m8n8.x2.shared.b16 {%0,%1}, [%2];"
                 : "=r"(r0), "=r"(r1) : "r"(addr));
}
__device__ __forceinline__ void mma16816(float& d0, float& d1, float& d2, float& d3,
                                         uint32_t a0, uint32_t a1, uint32_t a2, uint32_t a3,
                                         uint32_t b0, uint32_t b1) {
    asm volatile("mma.sync.aligned.m16n8k16.row.col.f32.f16.f16.f32 "
                 "{%0,%1,%2,%3}, {%4,%5,%6,%7}, {%8,%9}, {%0,%1,%2,%3};"
                 : "+f"(d0), "+f"(d1), "+f"(d2), "+f"(d3)
                 : "r"(a0), "r"(a1), "r"(a2), "r"(a3), "r"(b0), "r"(b1));
}
__device__ __forceinline__ void ffma2(unsigned long long& acc,
                                      unsigned long long a,
                                      unsigned long long b) {
    asm("fma.rn.f32x2 %0, %1, %2, %0;" : "+l"(acc) : "l"(a), "l"(b));
}
__device__ __forceinline__ unsigned long long pack2(float lo, float hi) {
    unsigned long long r;
    asm("mov.b64 %0, {%1, %2};" : "=l"(r) : "f"(lo), "f"(hi));
    return r;
}

// ---------------- W prep: one block, once ----------------
__global__ void wprep_kernel(const float* __restrict__ W1) {
    for (int t = threadIdx.x; t < 8192; t += 256) {
        int j = t & 127, k = t >> 7;
        float v = (j < 64) ? W1[k * 64 + j] : W1[(64 + k) * 64 + (j - 64)];
        g_Wt[j * 64 + k] = __float2half_rn(v);
    }
}

// ---------------- precompute: fp16 mma.sync, register-direct epilogue ----------------
// Per block: 64 nodes (M) x 128 outputs (N=[A|B]), K=64.
// 8 warps = 4 m-tiles (16 rows) x 2 n-strips (64 cols); 8 n-tiles x 4 k-steps per warp.
#define HSTR 72   // fp16 smem row stride (144B: 16B-aligned, conflict-free ldmatrix)

__global__ __launch_bounds__(256)
void precompute_kernel(const float* __restrict__ h,
                       const float* __restrict__ b1,
                       int n_nodes)
{
    __shared__ __half hh[64 * HSTR];     // h tile, 64x64 used
    __shared__ __half ww[128 * HSTR];    // W'^T : ww[j][k] = W'(k,j)

    const int tid   = threadIdx.x;
    const int node0 = blockIdx.x * 64;

    // hh: convert 64 node rows fp32 -> fp16
    const float4* h4 = (const float4*)h;
    #pragma unroll
    for (int i = tid; i < 1024; i += 256) {          // 64 rows x 16 float4
        int row = i >> 4, c4 = (i & 15) * 4;
        int node = node0 + row;
        float4 v = (node < n_nodes) ? h4[(size_t)node * 16 + (i & 15)]
                                    : make_float4(0.f, 0.f, 0.f, 0.f);
        *(half2*)&hh[row * HSTR + c4]     = __floats2half2_rn(v.x, v.y);
        *(half2*)&hh[row * HSTR + c4 + 2] = __floats2half2_rn(v.z, v.w);
    }
    // ww: vector-copy pre-transposed fp16 weights (4 x LDG.128 + STS.128 per thread)
    const uint4* Wt4 = (const uint4*)g_Wt;
    #pragma unroll
    for (int i = tid; i < 1024; i += 256) {          // 128 rows x 8 uint4
        int j = i >> 3, c8 = (i & 7) * 8;
        *(uint4*)&ww[j * HSTR + c8] = Wt4[i];
    }
    __syncthreads();

    const uint32_t hh_base = smem_u32(hh);
    const uint32_t ww_base = smem_u32(ww);
    const int w    = tid >> 5;
    const int lane = tid & 31;
    const int m0    = (w & 3) * 16;
    const int nbase = (w >> 2) * 64;

    // A fragments for all 4 k-steps (k16 each)
    uint32_t A[4][4];
    {
        int row = m0 + (lane & 15);
        int kh  = (lane >> 4) * 8;
        #pragma unroll
        for (int ks = 0; ks < 4; ++ks) {
            uint32_t addr = hh_base + (uint32_t)(row * HSTR + ks * 16 + kh) * 2u;
            ldsm_x4(A[ks][0], A[ks][1], A[ks][2], A[ks][3], addr);
        }
    }

    const int brow = (lane & 7);
    const int bkh  = ((lane >> 3) & 1) * 8;
    const int r    = lane >> 2;
    const int cpos = (lane & 3) * 2;

    #pragma unroll
    for (int nt = 0; nt < 8; ++nt) {
        int n0 = nbase + nt * 8;
        float c0 = 0.f, c1 = 0.f, c2 = 0.f, c3 = 0.f;
        #pragma unroll
        for (int ks = 0; ks < 4; ++ks) {
            uint32_t bb0, bb1;
            uint32_t addr = ww_base + (uint32_t)((n0 + brow) * HSTR + ks * 16 + bkh) * 2u;
            ldsm_x2(bb0, bb1, addr);
            mma16816(c0, c1, c2, c3, A[ks][0], A[ks][1], A[ks][2], A[ks][3], bb0, bb1);
        }
        int col   = n0 + cpos;
        int nodeA = node0 + m0 + r;
        int nodeB = nodeA + 8;
        if (col < 64) {
            float2 bpair = *(const float2*)&b1[col];
            if (nodeA < n_nodes)
                *(half2*)&g_A[(size_t)nodeA * HF + col] = __floats2half2_rn(c0 + bpair.x, c1 + bpair.y);
            if (nodeB < n_nodes)
                *(half2*)&g_A[(size_t)nodeB * HF + col] = __floats2half2_rn(c2 + bpair.x, c3 + bpair.y);
        } else {
            int cb = col - 64;
            if (nodeA < n_nodes)
                *(half2*)&g_B[(size_t)nodeA * HF + cb] = __floats2half2_rn(c0, c1);
            if (nodeB < n_nodes)
                *(half2*)&g_B[(size_t)nodeB * HF + cb] = __floats2half2_rn(c2, c3);
        }
    }
}

// ---------------- edge scoring: batched fp16 gather (L1-bypass), packed math ----------------
__global__ __launch_bounds__(256)
void edge_kernel(const int* __restrict__ src,
                 const int* __restrict__ dst,
                 const float* __restrict__ W2,
                 const float* __restrict__ b2,
                 float* __restrict__ out, int n_edges)
{
    const int lane = threadIdx.x & 31;
    const int sub  = lane >> 3;   // 0..3
    const int l    = lane & 7;    // feature group (8 halves = 16 B)
    const int warp = blockIdx.x * 8 + (threadIdx.x >> 5);
    const int ebase = warp * 16 + sub;   // edges ebase + 4k, k=0..3

    int ec[4], s[4], d[4];
    #pragma unroll
    for (int k = 0; k < 4; ++k) {
        int e = ebase + k * 4;
        ec[k] = (e < n_edges) ? e : (n_edges - 1);
    }
    #pragma unroll
    for (int k = 0; k < 4; ++k) s[k] = src[ec[k]];
    #pragma unroll
    for (int k = 0; k < 4; ++k) d[k] = dst[ec[k]];

    const uint4* A4 = (const uint4*)g_A;   // 8 x uint4 per node row
    const uint4* B4 = (const uint4*)g_B;
    uint4 av[4], bv[4];
    #pragma unroll
    for (int k = 0; k < 4; ++k) av[k] = __ldcg(&A4[(size_t)s[k] * 8 + l]);
    #pragma unroll
    for (int k = 0; k < 4; ++k) bv[k] = __ldcg(&B4[(size_t)d[k] * 8 + l]);

    const float4* W24 = (const float4*)W2;
    float4 w0 = W24[l * 2];
    float4 w1 = W24[l * 2 + 1];
    unsigned long long wp0 = pack2(w0.x, w0.y);
    unsigned long long wp1 = pack2(w0.z, w0.w);
    unsigned long long wp2 = pack2(w1.x, w1.y);
    unsigned long long wp3 = pack2(w1.z, w1.w);
    float bias = b2[0];

    const __half2 hz = __float2half2_rn(0.f);

    #pragma unroll
    for (int k = 0; k < 4; ++k) {
        const __half2* ah = (const __half2*)&av[k];
        const __half2* bh = (const __half2*)&bv[k];

        unsigned long long acc2 = 0ull;
        {
            __half2 v0 = __hmax2(__hadd2(ah[0], bh[0]), hz);
            float2 f0 = __half22float2(v0);
            ffma2(acc2, pack2(f0.x, f0.y), wp0);
            __half2 v1 = __hmax2(__hadd2(ah[1], bh[1]), hz);
            float2 f1 = __half22float2(v1);
            ffma2(acc2, pack2(f1.x, f1.y), wp1);
            __half2 v2 = __hmax2(__hadd2(ah[2], bh[2]), hz);
            float2 f2 = __half22float2(v2);
            ffma2(acc2, pack2(f2.x, f2.y), wp2);
            __half2 v3 = __hmax2(__hadd2(ah[3], bh[3]), hz);
            float2 f3 = __half22float2(v3);
            ffma2(acc2, pack2(f3.x, f3.y), wp3);
        }

        float2 rr = *(float2*)&acc2;
        float acc = rr.x + rr.y;

        acc += __shfl_xor_sync(0xffffffffu, acc, 4);
        acc += __shfl_xor_sync(0xffffffffu, acc, 2);
        acc += __shfl_xor_sync(0xffffffffu, acc, 1);

        int e = ebase + k * 4;
        if (l == 0 && e < n_edges) out[e] = acc + bias;
    }
}

extern "C" void kernel_launch(void* const* d_in, const int* in_sizes, int n_in,
                              void* d_out, int out_size)
{
    const float* h   = (const float*)d_in[0];
    const int*   src = (const int*)d_in[1];
    const int*   dst = (const int*)d_in[2];
    const float* W1  = (const float*)d_in[3];
    const float* b1  = (const float*)d_in[4];
    const float* W2  = (const float*)d_in[5];
    const float* b2  = (const float*)d_in[6];
    float* out = (float*)d_out;

    int n_nodes = in_sizes[0] / HF;
    int n_edges = in_sizes[1];

    wprep_kernel<<<1, 256>>>(W1);
    precompute_kernel<<<(n_nodes + 63) / 64, 256>>>(h, b1, n_nodes);
    // 16 edges per warp, 8 warps per block -> 128 edges per block
    edge_kernel<<<(n_edges + 127) / 128, 256>>>(src, dst, W2, b2, out, n_edges);
}

// round 15
// speedup vs baseline: 1.1598x; 1.1598x over previous
#include <cuda_runtime.h>
#include <cuda_fp16.h>
#include <cstdint>

#define HF 64
#define MAX_NODES 100000

// Scratch tables in fp16: A[n] = h[n]@W1[:64] + b1,  B[n] = h[n]@W1[64:]
__device__ __half g_A[MAX_NODES * HF];
__device__ __half g_B[MAX_NODES * HF];
// Pre-transposed fp16 W': g_Wt[j*64+k] = W'(k,j); j<64 -> W1s, j>=64 -> W1d
__device__ __half g_Wt[128 * 64];

// ---------------- PTX helpers ----------------
__device__ __forceinline__ uint32_t smem_u32(const void* p) {
    uint32_t a;
    asm("{ .reg .u64 t; cvta.to.shared.u64 t, %1; cvt.u32.u64 %0, t; }"
        : "=r"(a) : "l"(p));
    return a;
}
__device__ __forceinline__ void ldsm_x4(uint32_t& r0, uint32_t& r1,
                                        uint32_t& r2, uint32_t& r3, uint32_t addr) {
    asm volatile("ldmatrix.sync.aligned.m8n8.x4.shared.b16 {%0,%1,%2,%3}, [%4];"
                 : "=r"(r0), "=r"(r1), "=r"(r2), "=r"(r3) : "r"(addr));
}
__device__ __forceinline__ void ldsm_x2(uint32_t& r0, uint32_t& r1, uint32_t addr) {
    asm volatile("ldmatrix.sync.aligned.m8n8.x2.shared.b16 {%0,%1}, [%2];"
                 : "=r"(r0), "=r"(r1) : "r"(addr));
}
__device__ __forceinline__ void mma16816(float& d0, float& d1, float& d2, float& d3,
                                         uint32_t a0, uint32_t a1, uint32_t a2, uint32_t a3,
                                         uint32_t b0, uint32_t b1) {
    asm volatile("mma.sync.aligned.m16n8k16.row.col.f32.f16.f16.f32 "
                 "{%0,%1,%2,%3}, {%4,%5,%6,%7}, {%8,%9}, {%0,%1,%2,%3};"
                 : "+f"(d0), "+f"(d1), "+f"(d2), "+f"(d3)
                 : "r"(a0), "r"(a1), "r"(a2), "r"(a3), "r"(b0), "r"(b1));
}
__device__ __forceinline__ void ffma2(unsigned long long& acc,
                                      unsigned long long a,
                                      unsigned long long b) {
    asm("fma.rn.f32x2 %0, %1, %2, %0;" : "+l"(acc) : "l"(a), "l"(b));
}
__device__ __forceinline__ unsigned long long pack2(float lo, float hi) {
    unsigned long long r;
    asm("mov.b64 %0, {%1, %2};" : "=l"(r) : "f"(lo), "f"(hi));
    return r;
}

// ---------------- W prep: 32 blocks, one element per thread ----------------
__global__ void wprep_kernel(const float* __restrict__ W1) {
    int t = blockIdx.x * 256 + threadIdx.x;   // 0..8191
    int j = t & 127, k = t >> 7;
    float v = (j < 64) ? W1[k * 64 + j] : W1[(64 + k) * 64 + (j - 64)];
    g_Wt[j * 64 + k] = __float2half_rn(v);
}

// ---------------- precompute: fp16 mma.sync, register-direct epilogue ----------------
// Per block: 64 nodes (M) x 128 outputs (N=[A|B]), K=64.
// 8 warps = 4 m-tiles (16 rows) x 2 n-strips (64 cols); 8 n-tiles x 4 k-steps per warp.
#define HSTR 72   // fp16 smem row stride (144B: 16B-aligned, conflict-free ldmatrix)

__global__ __launch_bounds__(256)
void precompute_kernel(const float* __restrict__ h,
                       const float* __restrict__ b1,
                       int n_nodes)
{
    __shared__ __half hh[64 * HSTR];     // h tile, 64x64 used
    __shared__ __half ww[128 * HSTR];    // W'^T : ww[j][k] = W'(k,j)

    const int tid   = threadIdx.x;
    const int node0 = blockIdx.x * 64;

    // hh: convert 64 node rows fp32 -> fp16
    const float4* h4 = (const float4*)h;
    #pragma unroll
    for (int i = tid; i < 1024; i += 256) {          // 64 rows x 16 float4
        int row = i >> 4, c4 = (i & 15) * 4;
        int node = node0 + row;
        float4 v = (node < n_nodes) ? h4[(size_t)node * 16 + (i & 15)]
                                    : make_float4(0.f, 0.f, 0.f, 0.f);
        *(half2*)&hh[row * HSTR + c4]     = __floats2half2_rn(v.x, v.y);
        *(half2*)&hh[row * HSTR + c4 + 2] = __floats2half2_rn(v.z, v.w);
    }
    // ww: vector-copy pre-transposed fp16 weights (4 x LDG.128 + STS.128 per thread)
    const uint4* Wt4 = (const uint4*)g_Wt;
    #pragma unroll
    for (int i = tid; i < 1024; i += 256) {          // 128 rows x 8 uint4
        int j = i >> 3, c8 = (i & 7) * 8;
        *(uint4*)&ww[j * HSTR + c8] = Wt4[i];
    }
    __syncthreads();

    const uint32_t hh_base = smem_u32(hh);
    const uint32_t ww_base = smem_u32(ww);
    const int w    = tid >> 5;
    const int lane = tid & 31;
    const int m0    = (w & 3) * 16;
    const int nbase = (w >> 2) * 64;

    // A fragments for all 4 k-steps (k16 each)
    uint32_t A[4][4];
    {
        int row = m0 + (lane & 15);
        int kh  = (lane >> 4) * 8;
        #pragma unroll
        for (int ks = 0; ks < 4; ++ks) {
            uint32_t addr = hh_base + (uint32_t)(row * HSTR + ks * 16 + kh) * 2u;
            ldsm_x4(A[ks][0], A[ks][1], A[ks][2], A[ks][3], addr);
        }
    }

    const int brow = (lane & 7);
    const int bkh  = ((lane >> 3) & 1) * 8;
    const int r    = lane >> 2;
    const int cpos = (lane & 3) * 2;

    #pragma unroll
    for (int nt = 0; nt < 8; ++nt) {
        int n0 = nbase + nt * 8;
        float c0 = 0.f, c1 = 0.f, c2 = 0.f, c3 = 0.f;
        #pragma unroll
        for (int ks = 0; ks < 4; ++ks) {
            uint32_t bb0, bb1;
            uint32_t addr = ww_base + (uint32_t)((n0 + brow) * HSTR + ks * 16 + bkh) * 2u;
            ldsm_x2(bb0, bb1, addr);
            mma16816(c0, c1, c2, c3, A[ks][0], A[ks][1], A[ks][2], A[ks][3], bb0, bb1);
        }
        int col   = n0 + cpos;
        int nodeA = node0 + m0 + r;
        int nodeB = nodeA + 8;
        if (col < 64) {
            float2 bpair = *(const float2*)&b1[col];
            if (nodeA < n_nodes)
                *(half2*)&g_A[(size_t)nodeA * HF + col] = __floats2half2_rn(c0 + bpair.x, c1 + bpair.y);
            if (nodeB < n_nodes)
                *(half2*)&g_A[(size_t)nodeB * HF + col] = __floats2half2_rn(c2 + bpair.x, c3 + bpair.y);
        } else {
            int cb = col - 64;
            if (nodeA < n_nodes)
                *(half2*)&g_B[(size_t)nodeA * HF + cb] = __floats2half2_rn(c0, c1);
            if (nodeB < n_nodes)
                *(half2*)&g_B[(size_t)nodeB * HF + cb] = __floats2half2_rn(c2, c3);
        }
    }
}

// ---------------- edge scoring: batched fp16 gather (L1-bypass), packed math ----------------
__global__ __launch_bounds__(256)
void edge_kernel(const int* __restrict__ src,
                 const int* __restrict__ dst,
                 const float* __restrict__ W2,
                 const float* __restrict__ b2,
                 float* __restrict__ out, int n_edges)
{
    const int lane = threadIdx.x & 31;
    const int sub  = lane >> 3;   // 0..3
    const int l    = lane & 7;    // feature group (8 halves = 16 B)
    const int warp = blockIdx.x * 8 + (threadIdx.x >> 5);
    const int ebase = warp * 16 + sub;   // edges ebase + 4k, k=0..3

    int ec[4], s[4], d[4];
    #pragma unroll
    for (int k = 0; k < 4; ++k) {
        int e = ebase + k * 4;
        ec[k] = (e < n_edges) ? e : (n_edges - 1);
    }
    #pragma unroll
    for (int k = 0; k < 4; ++k) s[k] = src[ec[k]];
    #pragma unroll
    for (int k = 0; k < 4; ++k) d[k] = dst[ec[k]];

    const uint4* A4 = (const uint4*)g_A;   // 8 x uint4 per node row
    const uint4* B4 = (const uint4*)g_B;
    uint4 av[4], bv[4];
    #pragma unroll
    for (int k = 0; k < 4; ++k) av[k] = __ldcg(&A4[(size_t)s[k] * 8 + l]);
    #pragma unroll
    for (int k = 0; k < 4; ++k) bv[k] = __ldcg(&B4[(size_t)d[k] * 8 + l]);

    const float4* W24 = (const float4*)W2;
    float4 w0 = W24[l * 2];
    float4 w1 = W24[l * 2 + 1];
    unsigned long long wp0 = pack2(w0.x, w0.y);
    unsigned long long wp1 = pack2(w0.z, w0.w);
    unsigned long long wp2 = pack2(w1.x, w1.y);
    unsigned long long wp3 = pack2(w1.z, w1.w);
    float bias = b2[0];

    const __half2 hz = __float2half2_rn(0.f);

    #pragma unroll
    for (int k = 0; k < 4; ++k) {
        const __half2* ah = (const __half2*)&av[k];
        const __half2* bh = (const __half2*)&bv[k];

        unsigned long long acc2 = 0ull;
        {
            __half2 v0 = __hmax2(__hadd2(ah[0], bh[0]), hz);
            float2 f0 = __half22float2(v0);
            ffma2(acc2, pack2(f0.x, f0.y), wp0);
            __half2 v1 = __hmax2(__hadd2(ah[1], bh[1]), hz);
            float2 f1 = __half22float2(v1);
            ffma2(acc2, pack2(f1.x, f1.y), wp1);
            __half2 v2 = __hmax2(__hadd2(ah[2], bh[2]), hz);
            float2 f2 = __half22float2(v2);
            ffma2(acc2, pack2(f2.x, f2.y), wp2);
            __half2 v3 = __hmax2(__hadd2(ah[3], bh[3]), hz);
            float2 f3 = __half22float2(v3);
            ffma2(acc2, pack2(f3.x, f3.y), wp3);
        }

        float2 rr = *(float2*)&acc2;
        float acc = rr.x + rr.y;

        acc += __shfl_xor_sync(0xffffffffu, acc, 4);
        acc += __shfl_xor_sync(0xffffffffu, acc, 2);
        acc += __shfl_xor_sync(0xffffffffu, acc, 1);

        int e = ebase + k * 4;
        if (l == 0 && e < n_edges) out[e] = acc + bias;
    }
}

extern "C" void kernel_launch(void* const* d_in, const int* in_sizes, int n_in,
                              void* d_out, int out_size)
{
    const float* h   = (const float*)d_in[0];
    const int*   src = (const int*)d_in[1];
    const int*   dst = (const int*)d_in[2];
    const float* W1  = (const float*)d_in[3];
    const float* b1  = (const float*)d_in[4];
    const float* W2  = (const float*)d_in[5];
    const float* b2  = (const float*)d_in[6];
    float* out = (float*)d_out;

    int n_nodes = in_sizes[0] / HF;
    int n_edges = in_sizes[1];

    wprep_kernel<<<32, 256>>>(W1);
    precompute_kernel<<<(n_nodes + 63) / 64, 256>>>(h, b1, n_nodes);
    // 16 edges per warp, 8 warps per block -> 128 edges per block
    edge_kernel<<<(n_edges + 127) / 128, 256>>>(src, dst, W2, b2, out, n_edges);
}

// round 16
// speedup vs baseline: 1.1797x; 1.0172x over previous
#include <cuda_runtime.h>
#include <cuda_fp16.h>
#include <cstdint>

#define HF 64
#define MAX_NODES 100000

// Scratch tables in fp16: A[n] = h[n]@W1[:64] + b1,  B[n] = h[n]@W1[64:]
__device__ __half g_A[MAX_NODES * HF];
__device__ __half g_B[MAX_NODES * HF];

// ---------------- PTX helpers ----------------
__device__ __forceinline__ uint32_t smem_u32(const void* p) {
    uint32_t a;
    asm("{ .reg .u64 t; cvta.to.shared.u64 t, %1; cvt.u32.u64 %0, t; }"
        : "=r"(a) : "l"(p));
    return a;
}
__device__ __forceinline__ void ldsm_x4(uint32_t& r0, uint32_t& r1,
                                        uint32_t& r2, uint32_t& r3, uint32_t addr) {
    asm volatile("ldmatrix.sync.aligned.m8n8.x4.shared.b16 {%0,%1,%2,%3}, [%4];"
                 : "=r"(r0), "=r"(r1), "=r"(r2), "=r"(r3) : "r"(addr));
}
__device__ __forceinline__ void ldsm_x2_trans(uint32_t& r0, uint32_t& r1, uint32_t addr) {
    asm volatile("ldmatrix.sync.aligned.m8n8.x2.trans.shared.b16 {%0,%1}, [%2];"
                 : "=r"(r0), "=r"(r1) : "r"(addr));
}
__device__ __forceinline__ void mma16816(float& d0, float& d1, float& d2, float& d3,
                                         uint32_t a0, uint32_t a1, uint32_t a2, uint32_t a3,
                                         uint32_t b0, uint32_t b1) {
    asm volatile("mma.sync.aligned.m16n8k16.row.col.f32.f16.f16.f32 "
                 "{%0,%1,%2,%3}, {%4,%5,%6,%7}, {%8,%9}, {%0,%1,%2,%3};"
                 : "+f"(d0), "+f"(d1), "+f"(d2), "+f"(d3)
                 : "r"(a0), "r"(a1), "r"(a2), "r"(a3), "r"(b0), "r"(b1));
}
__device__ __forceinline__ void ffma2(unsigned long long& acc,
                                      unsigned long long a,
                                      unsigned long long b) {
    asm("fma.rn.f32x2 %0, %1, %2, %0;" : "+l"(acc) : "l"(a), "l"(b));
}
__device__ __forceinline__ unsigned long long pack2(float lo, float hi) {
    unsigned long long r;
    asm("mov.b64 %0, {%1, %2};" : "=l"(r) : "f"(lo), "f"(hi));
    return r;
}

// ---------------- precompute: fp16 mma.sync, ldmatrix.trans B, register epilogue --------
// Per block: 64 nodes (M) x 128 outputs (N=[A|B]), K=64.
// 8 warps = 4 m-tiles (16 rows) x 2 n-strips (64 cols); 8 n-tiles x 4 k-steps per warp.
// W staged in NATURAL layout: wsm[r][j] = W1[r][j] (r=0..127), B frags via ldmatrix.trans.
#define HSTR 72   // fp16 smem row stride (144B = 9*16B: aligned, conflict-free)

__global__ __launch_bounds__(256)
void precompute_kernel(const float* __restrict__ h,
                       const float* __restrict__ W1,
                       const float* __restrict__ b1,
                       int n_nodes)
{
    __shared__ __half hh[64 * HSTR];      // h tile, 64x64 used
    __shared__ __half wsm[128 * HSTR];    // W1 natural: wsm[r*HSTR + j]

    const int tid   = threadIdx.x;
    const int node0 = blockIdx.x * 64;

    // hh: convert 64 node rows fp32 -> fp16
    const float4* h4 = (const float4*)h;
    #pragma unroll
    for (int i = tid; i < 1024; i += 256) {          // 64 rows x 16 float4
        int row = i >> 4, c4 = (i & 15) * 4;
        int node = node0 + row;
        float4 v = (node < n_nodes) ? h4[(size_t)node * 16 + (i & 15)]
                                    : make_float4(0.f, 0.f, 0.f, 0.f);
        *(half2*)&hh[row * HSTR + c4]     = __floats2half2_rn(v.x, v.y);
        *(half2*)&hh[row * HSTR + c4 + 2] = __floats2half2_rn(v.z, v.w);
    }
    // wsm: convert W1 (128x64 fp32) -> fp16, natural layout, coalesced float4 reads
    const float4* W14 = (const float4*)W1;
    #pragma unroll
    for (int i = tid; i < 2048; i += 256) {          // 128 rows x 16 float4
        int r = i >> 4, c4 = (i & 15) * 4;
        float4 v = W14[i];
        *(half2*)&wsm[r * HSTR + c4]     = __floats2half2_rn(v.x, v.y);
        *(half2*)&wsm[r * HSTR + c4 + 2] = __floats2half2_rn(v.z, v.w);
    }
    __syncthreads();

    const uint32_t hh_base = smem_u32(hh);
    const uint32_t ww_base = smem_u32(wsm);
    const int w    = tid >> 5;
    const int lane = tid & 31;
    const int m0    = (w & 3) * 16;
    const int nbase = (w >> 2) * 64;     // 0 -> A strip (W1 rows 0-63), 64 -> B strip (rows 64-127)

    // A fragments for all 4 k-steps (k16 each)
    uint32_t A[4][4];
    {
        int row = m0 + (lane & 15);
        int kh  = (lane >> 4) * 8;
        #pragma unroll
        for (int ks = 0; ks < 4; ++ks) {
            uint32_t addr = hh_base + (uint32_t)(row * HSTR + ks * 16 + kh) * 2u;
            ldsm_x4(A[ks][0], A[ks][1], A[ks][2], A[ks][3], addr);
        }
    }

    const int trow = lane & 15;          // ldmatrix.trans row within k16 tile (lanes 0-15 used)
    const int r    = lane >> 2;
    const int cpos = (lane & 3) * 2;

    #pragma unroll
    for (int nt = 0; nt < 8; ++nt) {
        int n0 = nbase + nt * 8;
        int jcol = nt * 8;               // column within the 64-wide W half
        float c0 = 0.f, c1 = 0.f, c2 = 0.f, c3 = 0.f;
        #pragma unroll
        for (int ks = 0; ks < 4; ++ks) {
            uint32_t bb0, bb1;
            // natural-layout rows: nbase(0/64) selects W1s/W1d rows; k = ks*16 + trow
            uint32_t addr = ww_base +
                (uint32_t)((nbase + ks * 16 + trow) * HSTR + jcol) * 2u;
            ldsm_x2_trans(bb0, bb1, addr);
            mma16816(c0, c1, c2, c3, A[ks][0], A[ks][1], A[ks][2], A[ks][3], bb0, bb1);
        }
        int col   = n0 + cpos;
        int nodeA = node0 + m0 + r;
        int nodeB = nodeA + 8;
        if (col < 64) {
            float2 bpair = *(const float2*)&b1[col];
            if (nodeA < n_nodes)
                *(half2*)&g_A[(size_t)nodeA * HF + col] = __floats2half2_rn(c0 + bpair.x, c1 + bpair.y);
            if (nodeB < n_nodes)
                *(half2*)&g_A[(size_t)nodeB * HF + col] = __floats2half2_rn(c2 + bpair.x, c3 + bpair.y);
        } else {
            int cb = col - 64;
            if (nodeA < n_nodes)
                *(half2*)&g_B[(size_t)nodeA * HF + cb] = __floats2half2_rn(c0, c1);
            if (nodeB < n_nodes)
                *(half2*)&g_B[(size_t)nodeB * HF + cb] = __floats2half2_rn(c2, c3);
        }
    }
}

// ---------------- edge scoring: batched fp16 gather (L1-bypass), packed math ----------------
__global__ __launch_bounds__(256)
void edge_kernel(const int* __restrict__ src,
                 const int* __restrict__ dst,
                 const float* __restrict__ W2,
                 const float* __restrict__ b2,
                 float* __restrict__ out, int n_edges)
{
    const int lane = threadIdx.x & 31;
    const int sub  = lane >> 3;   // 0..3
    const int l    = lane & 7;    // feature group (8 halves = 16 B)
    const int warp = blockIdx.x * 8 + (threadIdx.x >> 5);
    const int ebase = warp * 16 + sub;   // edges ebase + 4k, k=0..3

    int ec[4], s[4], d[4];
    #pragma unroll
    for (int k = 0; k < 4; ++k) {
        int e = ebase + k * 4;
        ec[k] = (e < n_edges) ? e : (n_edges - 1);
    }
    #pragma unroll
    for (int k = 0; k < 4; ++k) s[k] = src[ec[k]];
    #pragma unroll
    for (int k = 0; k < 4; ++k) d[k] = dst[ec[k]];

    const uint4* A4 = (const uint4*)g_A;   // 8 x uint4 per node row
    const uint4* B4 = (const uint4*)g_B;
    uint4 av[4], bv[4];
    #pragma unroll
    for (int k = 0; k < 4; ++k) av[k] = __ldcg(&A4[(size_t)s[k] * 8 + l]);
    #pragma unroll
    for (int k = 0; k < 4; ++k) bv[k] = __ldcg(&B4[(size_t)d[k] * 8 + l]);

    const float4* W24 = (const float4*)W2;
    float4 w0 = W24[l * 2];
    float4 w1 = W24[l * 2 + 1];
    unsigned long long wp0 = pack2(w0.x, w0.y);
    unsigned long long wp1 = pack2(w0.z, w0.w);
    unsigned long long wp2 = pack2(w1.x, w1.y);
    unsigned long long wp3 = pack2(w1.z, w1.w);
    float bias = b2[0];

    const __half2 hz = __float2half2_rn(0.f);

    #pragma unroll
    for (int k = 0; k < 4; ++k) {
        const __half2* ah = (const __half2*)&av[k];
        const __half2* bh = (const __half2*)&bv[k];

        unsigned long long acc2 = 0ull;
        {
            __half2 v0 = __hmax2(__hadd2(ah[0], bh[0]), hz);
            float2 f0 = __half22float2(v0);
            ffma2(acc2, pack2(f0.x, f0.y), wp0);
            __half2 v1 = __hmax2(__hadd2(ah[1], bh[1]), hz);
            float2 f1 = __half22float2(v1);
            ffma2(acc2, pack2(f1.x, f1.y), wp1);
            __half2 v2 = __hmax2(__hadd2(ah[2], bh[2]), hz);
            float2 f2 = __half22float2(v2);
            ffma2(acc2, pack2(f2.x, f2.y), wp2);
            __half2 v3 = __hmax2(__hadd2(ah[3], bh[3]), hz);
            float2 f3 = __half22float2(v3);
            ffma2(acc2, pack2(f3.x, f3.y), wp3);
        }

        float2 rr = *(float2*)&acc2;
        float acc = rr.x + rr.y;

        acc += __shfl_xor_sync(0xffffffffu, acc, 4);
        acc += __shfl_xor_sync(0xffffffffu, acc, 2);
        acc += __shfl_xor_sync(0xffffffffu, acc, 1);

        int e = ebase + k * 4;
        if (l == 0 && e < n_edges) out[e] = acc + bias;
    }
}

extern "C" void kernel_launch(void* const* d_in, const int* in_sizes, int n_in,
                              void* d_out, int out_size)
{
    const float* h   = (const float*)d_in[0];
    const int*   src = (const int*)d_in[1];
    const int*   dst = (const int*)d_in[2];
    const float* W1  = (const float*)d_in[3];
    const float* b1  = (const float*)d_in[4];
    const float* W2  = (const float*)d_in[5];
    const float* b2  = (const float*)d_in[6];
    float* out = (float*)d_out;

    int n_nodes = in_sizes[0] / HF;
    int n_edges = in_sizes[1];

    precompute_kernel<<<(n_nodes + 63) / 64, 256>>>(h, W1, b1, n_nodes);
    // 16 edges per warp, 8 warps per block -> 128 edges per block
    edge_kernel<<<(n_edges + 127) / 128, 256>>>(src, dst, W2, b2, out, n_edges);
}